// round 16
// baseline (speedup 1.0000x reference)
#include <cuda_runtime.h>
#include <cuda_fp16.h>

#define USER_NUM 50000
#define N_NODES  100000
#define EMB      64
#define ROWB     128    // bytes per fp16 row
#define ADJ_NNZ  1600000
#define S_NNZ    800000
#define TOT      (N_NODES * EMB)
#define SB 512
#define ADJ_NB ((N_NODES + SB - 1) / SB)    // 196
#define S_NB   ((USER_NUM + SB - 1) / SB)   // 98

// ---------------- scratch (device globals; zero-initialized at load) ----------------
__device__ __half g_egoA[TOT];              // ego0 (fp16 copy of inputs)
__device__ __half g_egoB[TOT];              // ego1
__device__ __half g_egoC[TOT];              // ego2
__device__ __half g_hFull[TOT];             // [u' ; v] gather source for ADJ

__device__ int   g_adj_cnt[N_NODES];        // invariant: zero at kernel_launch entry
__device__ int   g_adj_ptr[N_NODES + 1];
__device__ int   g_adj_rank[ADJ_NNZ];       // per-edge within-row rank (from hist)
__device__ uint2 g_adj_cv[ADJ_NNZ];         // (col*128, val bits)

__device__ int   g_s_cnt[USER_NUM];         // invariant: zero at kernel_launch entry
__device__ int   g_s_ptr[USER_NUM + 1];
__device__ int   g_s_rank[S_NNZ];
__device__ uint2 g_s_cv[S_NNZ];             // (col*128, val bits)

__device__ int   g_bsumsA[SB];              // raw per-block sums (not pre-scanned)
__device__ int   g_bsumsB[SB];

// ---------------- fused: hist(adj) + hist(s) + rank record + init(ego0 fp16) ----------------
__global__ void hist_init_kernel(const int* __restrict__ adj_rows, const int* __restrict__ s_rows,
                                 int* __restrict__ adj_cnt, int* __restrict__ s_cnt,
                                 int* __restrict__ adj_rank, int* __restrict__ s_rank,
                                 const float* __restrict__ ue, const float* __restrict__ ie,
                                 __half* __restrict__ ego) {
    int i = blockIdx.x * blockDim.x + threadIdx.x;
    if (i < ADJ_NNZ) {
        adj_rank[i] = atomicAdd(adj_cnt + __ldcs(adj_rows + i), 1);
    } else if (i < ADJ_NNZ + S_NNZ) {
        int j = i - ADJ_NNZ;
        s_rank[j] = atomicAdd(s_cnt + __ldcs(s_rows + j), 1);
    } else if (i < ADJ_NNZ + S_NNZ + TOT / 2) {
        int j = i - (ADJ_NNZ + S_NNZ);             // half2/float2 index
        const float2* src = (j < USER_NUM * EMB / 2) ? (const float2*)ue
                                                     : (const float2*)ie - USER_NUM * EMB / 2;
        float2 v = src[j];
        ((__half2*)ego)[j] = __floats2half2_rn(v.x, v.y);
    }
}

// per-block exclusive scans of both count arrays; raw block sums out
__global__ void scan1_kernel(const int* __restrict__ adj_cnt, int* __restrict__ adj_ptr,
                             const int* __restrict__ s_cnt, int* __restrict__ s_ptr,
                             int* __restrict__ bsumsA, int* __restrict__ bsumsB) {
    __shared__ int sh[SB];
    const int* cnt; int* ptr; int* bsums; int n; int b;
    if (blockIdx.x < ADJ_NB) { cnt = adj_cnt; ptr = adj_ptr; bsums = bsumsA; n = N_NODES; b = blockIdx.x; }
    else                     { cnt = s_cnt;   ptr = s_ptr;   bsums = bsumsB; n = USER_NUM; b = blockIdx.x - ADJ_NB; }
    int i = b * SB + threadIdx.x;
    int v = (i < n) ? cnt[i] : 0;
    sh[threadIdx.x] = v;
    __syncthreads();
    for (int off = 1; off < SB; off <<= 1) {
        int t = (threadIdx.x >= off) ? sh[threadIdx.x - off] : 0;
        __syncthreads();
        sh[threadIdx.x] += t;
        __syncthreads();
    }
    if (i < n) ptr[i] = sh[threadIdx.x] - v;
    if (threadIdx.x == SB - 1) bsums[b] = sh[SB - 1];
}

// fused scan2+scan3: each block re-derives the block-sum prefixes in smem,
// then adds offsets, terminates rowptrs, re-zeroes cnt arrays.
__global__ void scan3_kernel(int* __restrict__ adj_ptr, int* __restrict__ s_ptr,
                             const int* __restrict__ bsumsA, const int* __restrict__ bsumsB,
                             int* __restrict__ adj_cnt, int* __restrict__ s_cnt) {
    __shared__ int shA[256];   // exclusive prefix of bsumsA (ADJ_NB=196 <= 256)
    __shared__ int shB[128];   // exclusive prefix of bsumsB (S_NB=98 <= 128)
    int t = threadIdx.x;
    if (t < 256) shA[t] = (t < ADJ_NB) ? bsumsA[t] : 0;
    if (t < 128) shB[t] = (t < S_NB)   ? bsumsB[t] : 0;
    __syncthreads();
    int vA = (t < 256) ? shA[t] : 0;
    int vB = (t < 128) ? shB[t] : 0;
    for (int off = 1; off < 256; off <<= 1) {
        int ta = (t < 256 && t >= off) ? shA[t - off] : 0;
        int tb = (t < 128 && t >= off && off < 128) ? shB[t - off] : 0;
        __syncthreads();
        if (t < 256) shA[t] += ta;
        if (t < 128 && off < 128) shB[t] += tb;
        __syncthreads();
    }
    if (t < 256) shA[t] -= vA;   // inclusive -> exclusive
    if (t < 128) shB[t] -= vB;
    __syncthreads();

    int i = blockIdx.x * blockDim.x + t;
    if (i < N_NODES) {
        int p = adj_ptr[i] + shA[i / SB];
        adj_ptr[i] = p; adj_cnt[i] = 0;
        if (i == 0) adj_ptr[N_NODES] = ADJ_NNZ;
    } else if (i < N_NODES + USER_NUM) {
        int j = i - N_NODES;
        int p = s_ptr[j] + shB[j / SB];
        s_ptr[j] = p; s_cnt[j] = 0;
        if (j == 0) s_ptr[USER_NUM] = S_NNZ;
    }
}

// atomic-free S scatter only: p = s_ptr[row] + rank[i]
__global__ void s_scatter_kernel(const int* __restrict__ s_rows, const int* __restrict__ s_cols,
                                 const float* __restrict__ s_vals, const int* __restrict__ s_rank,
                                 const int* __restrict__ s_ptr, uint2* __restrict__ s_cv) {
    int i = blockIdx.x * blockDim.x + threadIdx.x;
    if (i < S_NNZ) {
        int p = __ldg(s_ptr + __ldcs(s_rows + i)) + __ldcs(s_rank + i);
        s_cv[p] = make_uint2((unsigned)__ldcs(s_cols + i) * ROWB,
                             __float_as_uint(__ldcs(s_vals + i)));
    }
}

// ---------------- warp-per-row gather core (single base, byte-offset cols, MLP-4) ----------------
__device__ __forceinline__ float2 row_accum(const uint2* __restrict__ cv, int e, int end,
                                            int lane, const char* __restrict__ base, float2 a) {
    const int lb = lane * 4;   // byte offset of this lane's half2 within a row
    for (; e + 3 < end; e += 4) {
        uint2 c0 = __ldg(cv + e),     c1 = __ldg(cv + e + 1);
        uint2 c2 = __ldg(cv + e + 2), c3 = __ldg(cv + e + 3);
        float2 x0 = __half22float2(__ldg((const __half2*)(base + c0.x + lb)));
        float2 x1 = __half22float2(__ldg((const __half2*)(base + c1.x + lb)));
        float2 x2 = __half22float2(__ldg((const __half2*)(base + c2.x + lb)));
        float2 x3 = __half22float2(__ldg((const __half2*)(base + c3.x + lb)));
        float w0 = __uint_as_float(c0.y), w1 = __uint_as_float(c1.y);
        float w2 = __uint_as_float(c2.y), w3 = __uint_as_float(c3.y);
        a.x = fmaf(w0, x0.x, fmaf(w1, x1.x, fmaf(w2, x2.x, fmaf(w3, x3.x, a.x))));
        a.y = fmaf(w0, x0.y, fmaf(w1, x1.y, fmaf(w2, x2.y, fmaf(w3, x3.y, a.y))));
    }
    for (; e < end; e++) {
        uint2 c0 = __ldg(cv + e);
        float w0 = __uint_as_float(c0.y);
        float2 x0 = __half22float2(__ldg((const __half2*)(base + c0.x + lb)));
        a.x = fmaf(w0, x0.x, a.x);
        a.y = fmaf(w0, x0.y, a.y);
    }
    return a;
}

// s_spmm body: rows < USER_NUM: hFull[r] = ego[r] + sum val*ego[col]; else passthrough
__device__ __forceinline__ void s_spmm_body(int row, int lane,
                                            const int* __restrict__ ptr,
                                            const uint2* __restrict__ cv,
                                            const __half* __restrict__ ego,
                                            __half* __restrict__ hFull) {
    __half2 self = ((const __half2*)(ego + (size_t)row * EMB))[lane];
    if (row < USER_NUM) {
        int e0 = __ldg(ptr + row), end = __ldg(ptr + row + 1);
        float2 a = __half22float2(self);
        a = row_accum(cv, e0, end, lane, (const char*)ego, a);
        ((__half2*)(hFull + (size_t)row * EMB))[lane] = __floats2half2_rn(a.x, a.y);
    } else {
        ((__half2*)(hFull + (size_t)row * EMB))[lane] = self;
    }
}

// standalone s_spmm (layers 1, 2)
__global__ void s_spmm_kernel(const int* __restrict__ ptr, const uint2* __restrict__ cv,
                              const __half* __restrict__ ego, __half* __restrict__ hFull) {
    int row = blockIdx.x * (blockDim.x >> 5) + (threadIdx.x >> 5);
    if (row >= N_NODES) return;
    s_spmm_body(row, threadIdx.x & 31, ptr, cv, ego, hFull);
}

// fused: blocks [0, S_SPMM_BLOCKS) run s_spmm layer 0; remaining blocks run adj scatter.
#define S_SPMM_BLOCKS ((N_NODES * 32 + 255) / 256)          // 12500
#define ADJ_SCAT_BLOCKS ((ADJ_NNZ + 255) / 256)             // 6250
__global__ void sspmm0_adjscatter_kernel(
    const int* __restrict__ s_ptr, const uint2* __restrict__ s_cv,
    const __half* __restrict__ ego, __half* __restrict__ hFull,
    const int* __restrict__ adj_rows, const int* __restrict__ adj_cols,
    const float* __restrict__ adj_vals, const int* __restrict__ adj_rank,
    const int* __restrict__ adj_ptr, uint2* __restrict__ adj_cv) {
    if (blockIdx.x < S_SPMM_BLOCKS) {
        int row = blockIdx.x * (blockDim.x >> 5) + (threadIdx.x >> 5);
        if (row >= N_NODES) return;
        s_spmm_body(row, threadIdx.x & 31, s_ptr, s_cv, ego, hFull);
    } else {
        int i = (blockIdx.x - S_SPMM_BLOCKS) * blockDim.x + threadIdx.x;
        if (i < ADJ_NNZ) {
            int p = __ldg(adj_ptr + __ldcs(adj_rows + i)) + __ldcs(adj_rank + i);
            adj_cv[p] = make_uint2((unsigned)__ldcs(adj_cols + i) * ROWB,
                                   __float_as_uint(__ldcs(adj_vals + i)));
        }
    }
}

// a = sum val * hFull[col]
// last==0: nxt[r] = half(a)
// last==1: out[r] = (input_row + ego1[r] + ego2[r] + a) * 0.25  (ego param IS ego2 on last)
__global__ void adj_spmm_kernel(const int* __restrict__ ptr, const uint2* __restrict__ cv,
                                const __half* __restrict__ hFull, const __half* __restrict__ ego,
                                __half* __restrict__ nxt,
                                const float* __restrict__ ue, const float* __restrict__ ie,
                                const __half* __restrict__ ego1,
                                float* __restrict__ out, int last) {
    int row = blockIdx.x * (blockDim.x >> 5) + (threadIdx.x >> 5);
    int lane = threadIdx.x & 31;
    if (row >= N_NODES) return;
    int e0 = __ldg(ptr + row), end = __ldg(ptr + row + 1);
    float2 a = row_accum(cv, e0, end, lane, (const char*)hFull, make_float2(0.f, 0.f));
    if (last) {
        const float2* in0 = (row < USER_NUM)
            ? (const float2*)ue + (size_t)row * (EMB / 2)
            : (const float2*)ie + (size_t)(row - USER_NUM) * (EMB / 2);
        float2 v0 = __ldg(in0 + lane);                                            // ego0 (exact)
        float2 v1 = __half22float2(__ldg((const __half2*)(ego1 + (size_t)row * EMB) + lane));
        float2 v2 = __half22float2(__ldg((const __half2*)(ego  + (size_t)row * EMB) + lane));
        ((float2*)(out + (size_t)row * EMB))[lane] =
            make_float2((v0.x + v1.x + v2.x + a.x) * 0.25f,
                        (v0.y + v1.y + v2.y + a.y) * 0.25f);
    } else {
        ((__half2*)(nxt + (size_t)row * EMB))[lane] = __floats2half2_rn(a.x, a.y);
    }
}

extern "C" void kernel_launch(void* const* d_in, const int* in_sizes, int n_in,
                              void* d_out, int out_size) {
    const float* ue       = (const float*)d_in[0];
    const float* ie       = (const float*)d_in[1];
    const int*   adj_rows = (const int*)d_in[2];
    const int*   adj_cols = (const int*)d_in[3];
    const float* adj_vals = (const float*)d_in[4];
    const int*   s_rows   = (const int*)d_in[5];
    const int*   s_cols   = (const int*)d_in[6];
    const float* s_vals   = (const float*)d_in[7];

    __half *egoA, *egoB, *egoC, *hFull;
    int *adj_cnt, *adj_ptr, *adj_rank, *s_cnt, *s_ptr, *s_rank, *bsumsA, *bsumsB;
    uint2 *adj_cv, *s_cv;
    cudaGetSymbolAddress((void**)&egoA,     g_egoA);
    cudaGetSymbolAddress((void**)&egoB,     g_egoB);
    cudaGetSymbolAddress((void**)&egoC,     g_egoC);
    cudaGetSymbolAddress((void**)&hFull,    g_hFull);
    cudaGetSymbolAddress((void**)&adj_cnt,  g_adj_cnt);
    cudaGetSymbolAddress((void**)&adj_ptr,  g_adj_ptr);
    cudaGetSymbolAddress((void**)&adj_rank, g_adj_rank);
    cudaGetSymbolAddress((void**)&adj_cv,   g_adj_cv);
    cudaGetSymbolAddress((void**)&s_cnt,    g_s_cnt);
    cudaGetSymbolAddress((void**)&s_ptr,    g_s_ptr);
    cudaGetSymbolAddress((void**)&s_rank,   g_s_rank);
    cudaGetSymbolAddress((void**)&s_cv,     g_s_cv);
    cudaGetSymbolAddress((void**)&bsumsA,   g_bsumsA);
    cudaGetSymbolAddress((void**)&bsumsB,   g_bsumsB);

    const int TPB = 256;

    // ---- build CSR + init ego0 ----
    {
        int tot = ADJ_NNZ + S_NNZ + TOT / 2;
        hist_init_kernel<<<(tot + TPB - 1) / TPB, TPB>>>(adj_rows, s_rows, adj_cnt, s_cnt,
                                                         adj_rank, s_rank, ue, ie, egoA);
    }
    scan1_kernel<<<ADJ_NB + S_NB, SB>>>(adj_cnt, adj_ptr, s_cnt, s_ptr, bsumsA, bsumsB);
    {
        int tot = N_NODES + USER_NUM;
        scan3_kernel<<<(tot + TPB - 1) / TPB, TPB>>>(adj_ptr, s_ptr,
                                                     bsumsA, bsumsB, adj_cnt, s_cnt);
    }
    s_scatter_kernel<<<(S_NNZ + TPB - 1) / TPB, TPB>>>(s_rows, s_cols, s_vals, s_rank,
                                                       s_ptr, s_cv);

    // ---- fused: adj scatter || s_spmm layer 0 ----
    sspmm0_adjscatter_kernel<<<S_SPMM_BLOCKS + ADJ_SCAT_BLOCKS, TPB>>>(
        s_ptr, s_cv, egoA, hFull,
        adj_rows, adj_cols, adj_vals, adj_rank, adj_ptr, adj_cv);

    // ---- remaining layers ----
    const int wpb = TPB / 32;
    const int all_blocks = (N_NODES + wpb - 1) / wpb;

    adj_spmm_kernel<<<all_blocks, TPB>>>(adj_ptr, adj_cv, hFull, egoA, egoB,
                                         ue, ie, egoB, (float*)d_out, 0);
    s_spmm_kernel<<<all_blocks, TPB>>>(s_ptr, s_cv, egoB, hFull);
    adj_spmm_kernel<<<all_blocks, TPB>>>(adj_ptr, adj_cv, hFull, egoB, egoC,
                                         ue, ie, egoB, (float*)d_out, 0);
    s_spmm_kernel<<<all_blocks, TPB>>>(s_ptr, s_cv, egoC, hFull);
    adj_spmm_kernel<<<all_blocks, TPB>>>(adj_ptr, adj_cv, hFull, egoC, /*nxt*/egoA,
                                         ue, ie, egoB, (float*)d_out, 1);
}